// round 8
// baseline (speedup 1.0000x reference)
#include <cuda_runtime.h>
#include <math_constants.h>

// Scratch + sync state (allocation-free rule: __device__ globals).
__device__ int g_offsets[65537];
__device__ unsigned g_scan_done = 0;  // boundary chunks completed
__device__ unsigned g_blk_fini  = 0;  // pool blocks finished (for replay reset)

// ---------------------------------------------------------------------------
// Single fused kernel. Grid = G blocks (one per segment), 128 threads.
//
// Phase 1 (blocks 0..NB-1 only): vectorized boundary scan of one 1024-id
// chunk of the SORTED segment_ids (each thread owns 8 consecutive ids via
// int4/longlong2 loads + one scalar successor probe). At each transition
// id -> next, fill g_offsets for every segment in (id, next]. Release via
// atomicAdd on g_scan_done. NB = ceil(n / 1024) <= wave-1 residency (1776),
// so all scan blocks are co-resident with the first wave and no deadlock.
//
// Phase 2 (all blocks): spin (acquire) until all NB chunks are done, then
// pool segment g: 4 row-groups x 32 lanes, lane l owns features [4l,4l+4)
// via float4 streaming loads; cross-group combine in smem; thread (stat,l)
// writes one float4 streaming store.
//
// Replay reset: the last finishing block zeroes both counters so the next
// graph replay starts clean (deterministic across replays).
// ---------------------------------------------------------------------------
__global__ void __launch_bounds__(128, 12)
seg_pool_fused_kernel(const float* __restrict__ x, const void* __restrict__ seg,
                      float* __restrict__ out, int n, int G, int NB) {
    const int blk  = blockIdx.x;
    const int tid  = threadIdx.x;
    const int lane = tid & 31;
    const int grp  = tid >> 5;

    // ---------------- Phase 1: boundary scan (first NB blocks) ----------------
    if (blk < NB) {
        const int base = (blk * 128 + tid) * 8;
        if (base < n) {
            // dtype sniff (warp-uniform): int64 word at index n/4 covers int32
            // elements n/2, n/2+1. Sorted ids: middle element ~G/2 != 0, so
            // int32 data read as int64 is >= 2^32; real int64 stays small.
            const long long probe = ((const long long*)seg)[n >> 2];
            const bool is64 = (probe >= 0) && (probe < (1LL << 31));

            int v[9];  // 8 owned ids + successor (sentinel G past the end)
            if (base + 8 <= n) {
                if (is64) {
                    const longlong2* p =
                        (const longlong2*)((const long long*)seg + base);
                    #pragma unroll
                    for (int j = 0; j < 4; j++) {
                        longlong2 a = __ldg(&p[j]);
                        v[2 * j]     = (int)a.x;
                        v[2 * j + 1] = (int)a.y;
                    }
                } else {
                    const int4* p = (const int4*)((const int*)seg + base);
                    int4 a = __ldg(&p[0]);
                    int4 b = __ldg(&p[1]);
                    v[0] = a.x; v[1] = a.y; v[2] = a.z; v[3] = a.w;
                    v[4] = b.x; v[5] = b.y; v[6] = b.z; v[7] = b.w;
                }
                v[8] = (base + 8 < n)
                         ? (is64 ? (int)((const long long*)seg)[base + 8]
                                 : ((const int*)seg)[base + 8])
                         : G;
            } else {
                #pragma unroll
                for (int j = 0; j < 9; j++) {
                    const int idx = base + j;
                    v[j] = (idx < n)
                             ? (is64 ? (int)((const long long*)seg)[idx]
                                     : ((const int*)seg)[idx])
                             : G;
                }
            }

            if (base == 0) {
                for (int s = 0; s <= v[0]; s++) g_offsets[s] = 0;
            }
            #pragma unroll
            for (int j = 0; j < 8; j++) {
                for (int s = v[j] + 1; s <= v[j + 1]; s++)
                    g_offsets[s] = base + j + 1;
            }
        }
        __syncthreads();           // all chunk writes issued by this block
        if (tid == 0) {
            __threadfence();       // release g_offsets writes
            atomicAdd(&g_scan_done, 1u);
        }
    }

    // ---------------- Phase 2: wait for all scan chunks ----------------
    if (tid == 0) {
        unsigned v;
        do {
            asm volatile("ld.acquire.gpu.global.u32 %0, [%1];"
                         : "=r"(v) : "l"(&g_scan_done));
            if (v < (unsigned)NB) __nanosleep(200);
        } while (v < (unsigned)NB);
    }
    __syncthreads();

    const int g = blk;
    const int start = g_offsets[g];
    const int end   = g_offsets[g + 1];

    float4 s  = make_float4(0.f, 0.f, 0.f, 0.f);
    float4 q  = make_float4(0.f, 0.f, 0.f, 0.f);
    float4 mx = make_float4(-CUDART_INF_F, -CUDART_INF_F, -CUDART_INF_F, -CUDART_INF_F);
    float4 mn = make_float4( CUDART_INF_F,  CUDART_INF_F,  CUDART_INF_F,  CUDART_INF_F);

    const float4* __restrict__ xv = (const float4*)x;  // row stride = 32 float4

    #pragma unroll 4
    for (int r = start + grp; r < end; r += 4) {
        float4 v = __ldcs(&xv[(size_t)r * 32 + lane]);
        s.x += v.x; s.y += v.y; s.z += v.z; s.w += v.w;
        q.x = fmaf(v.x, v.x, q.x); q.y = fmaf(v.y, v.y, q.y);
        q.z = fmaf(v.z, v.z, q.z); q.w = fmaf(v.w, v.w, q.w);
        mx.x = fmaxf(mx.x, v.x); mx.y = fmaxf(mx.y, v.y);
        mx.z = fmaxf(mx.z, v.z); mx.w = fmaxf(mx.w, v.w);
        mn.x = fminf(mn.x, v.x); mn.y = fminf(mn.y, v.y);
        mn.z = fminf(mn.z, v.z); mn.w = fminf(mn.w, v.w);
    }

    // partials: [stat][group][lane] as float4 -> 8 KB
    // stat order = output order: 0=max, 1=min, 2=sum(->mean), 3=sumsq(->std)
    __shared__ float4 sm4[4][4][32];
    sm4[0][grp][lane] = mx;
    sm4[1][grp][lane] = mn;
    sm4[2][grp][lane] = s;
    sm4[3][grp][lane] = q;
    __syncthreads();

    // epilogue: thread (stat st=grp, lane l) combines the 4 group partials
    const int st = grp;
    const int l  = lane;
    const float cnt = (float)(end - start);

    float4 r = sm4[st][0][l];
    if (st == 0) {
        #pragma unroll
        for (int k = 1; k < 4; k++) {
            float4 t = sm4[0][k][l];
            r.x = fmaxf(r.x, t.x); r.y = fmaxf(r.y, t.y);
            r.z = fmaxf(r.z, t.z); r.w = fmaxf(r.w, t.w);
        }
    } else if (st == 1) {
        #pragma unroll
        for (int k = 1; k < 4; k++) {
            float4 t = sm4[1][k][l];
            r.x = fminf(r.x, t.x); r.y = fminf(r.y, t.y);
            r.z = fminf(r.z, t.z); r.w = fminf(r.w, t.w);
        }
    } else if (st == 2) {
        #pragma unroll
        for (int k = 1; k < 4; k++) {
            float4 t = sm4[2][k][l];
            r.x += t.x; r.y += t.y; r.z += t.z; r.w += t.w;
        }
        r.x /= cnt; r.y /= cnt; r.z /= cnt; r.w /= cnt;  // mean
    } else {
        float4 su = sm4[2][0][l];
        #pragma unroll
        for (int k = 1; k < 4; k++) {
            float4 tq = sm4[3][k][l];
            float4 ts = sm4[2][k][l];
            r.x += tq.x; r.y += tq.y; r.z += tq.z; r.w += tq.w;
            su.x += ts.x; su.y += ts.y; su.z += ts.z; su.w += ts.w;
        }
        const float inv = 1.0f / cnt;
        const float ax = su.x * inv, ay = su.y * inv,
                    az = su.z * inv, aw = su.w * inv;
        const float d = cnt - 1.0f;
        r.x = sqrtf(fmaxf((r.x - cnt * ax * ax) / d, 0.0f));
        r.y = sqrtf(fmaxf((r.y - cnt * ay * ay) / d, 0.0f));
        r.z = sqrtf(fmaxf((r.z - cnt * az * az) / d, 0.0f));
        r.w = sqrtf(fmaxf((r.w - cnt * aw * aw) / d, 0.0f));
    }

    // out[g][st][4l .. 4l+4): one coalesced 16B streaming store per thread
    float4* o4 = (float4*)(out + (size_t)g * 512 + st * 128);
    __stcs(&o4[l], r);

    // ---------------- Replay reset: last block zeroes the counters ----------
    __syncthreads();
    if (tid == 0) {
        __threadfence();
        unsigned old = atomicAdd(&g_blk_fini, 1u);
        if (old == (unsigned)(gridDim.x - 1)) {
            atomicExch(&g_scan_done, 0u);
            atomicExch(&g_blk_fini, 0u);
            __threadfence();
        }
    }
}

extern "C" void kernel_launch(void* const* d_in, const int* in_sizes, int n_in,
                              void* d_out, int out_size) {
    const float* x   = (const float*)d_in[0];
    const void*  seg = d_in[1];
    float* out = (float*)d_out;

    const int D = 128;
    const int n = in_sizes[0] / D;          // number of rows
    const int G = out_size / (4 * D);       // number of segments

    // scan chunk = 128 threads * 8 ids = 1024 ids per block
    const int NB = (n + 1023) / 1024;       // 1024 for n = 1M

    seg_pool_fused_kernel<<<G, 128>>>(x, seg, out, n, G, NB);
}